// round 1
// baseline (speedup 1.0000x reference)
#include <cuda_runtime.h>
#include <cuda_bf16.h>

#define HW   2304
#define CIN  256
#define CMID 16
#define NB   4
#define PIX_PER_WARP 8
#define WARPS_K1 8
#define PIX_PER_BLOCK (PIX_PER_WARP * WARPS_K1)   // 64
#define BLOCKS_PER_BATCH (HW / PIX_PER_BLOCK)     // 36

// Scratch (static device globals — no allocations allowed)
__device__ float g_v  [NB][HW][2];
__device__ float g_mo [NB][HW][2];
__device__ float g_part[NB][BLOCKS_PER_BATCH][2];
__device__ float g_prm[NB][HW][5];   // ic0, ic1, scale, m0, m1

// ---------------------------------------------------------------------------
// Kernel 1: per-pixel 256->16 projection, tanh, 16->2 projections,
//           per-block partial sums for the batch normalization.
// One warp per pixel; map_w staged in shared memory.
// ---------------------------------------------------------------------------
__global__ __launch_bounds__(256) void k1(
    const float* __restrict__ x,
    const float* __restrict__ map_w,  const float* __restrict__ map_b,
    const float* __restrict__ mean_w, const float* __restrict__ mean_b,
    const float* __restrict__ cov_w,  const float* __restrict__ cov_b)
{
    __shared__ float sw[CMID * CIN];        // 16 KB of weights
    const int b    = blockIdx.y;
    const int tid  = threadIdx.x;
    const int warp = tid >> 5;
    const int lane = tid & 31;

    for (int i = tid; i < CMID * CIN; i += 256) sw[i] = map_w[i];
    __syncthreads();

    float lsum = 0.f, lsq = 0.f;   // meaningful on lane 0 only

    for (int pp = 0; pp < PIX_PER_WARP; ++pp) {
        const int pix = blockIdx.x * PIX_PER_BLOCK + warp * PIX_PER_WARP + pp;
        const float* xr = x + ((long)b * HW + pix) * CIN;

        float xv[8];
        #pragma unroll
        for (int kk = 0; kk < 8; ++kk) xv[kk] = xr[lane + 32 * kk];

        float acc[CMID];
        #pragma unroll
        for (int c = 0; c < CMID; ++c) {
            float a = 0.f;
            #pragma unroll
            for (int kk = 0; kk < 8; ++kk)
                a = fmaf(xv[kk], sw[c * CIN + lane + 32 * kk], a);
            acc[c] = a;
        }

        // butterfly-reduce all 16 accumulators across the warp
        #pragma unroll
        for (int off = 16; off; off >>= 1) {
            #pragma unroll
            for (int c = 0; c < CMID; ++c)
                acc[c] += __shfl_xor_sync(0xffffffffu, acc[c], off);
        }

        if (lane == 0) {
            float t[CMID];
            #pragma unroll
            for (int c = 0; c < CMID; ++c)
                t[c] = tanhf(acc[c] + __ldg(&map_b[c]));

            float mo0 = __ldg(&mean_b[0]), mo1 = __ldg(&mean_b[1]);
            float v0  = __ldg(&cov_b[0]),  v1  = __ldg(&cov_b[1]);
            #pragma unroll
            for (int c = 0; c < CMID; ++c) {
                mo0 = fmaf(t[c], __ldg(&mean_w[c]),        mo0);
                mo1 = fmaf(t[c], __ldg(&mean_w[CMID + c]), mo1);
                v0  = fmaf(t[c], __ldg(&cov_w[c]),         v0);
                v1  = fmaf(t[c], __ldg(&cov_w[CMID + c]),  v1);
            }
            g_mo[b][pix][0] = mo0;  g_mo[b][pix][1] = mo1;
            g_v [b][pix][0] = v0;   g_v [b][pix][1] = v1;
            lsum += v0 + v1;
            lsq  += v0 * v0 + v1 * v1;
        }
    }

    // deterministic per-block reduction of the lane-0 partials
    __shared__ float ss[WARPS_K1][2];
    if (lane == 0) { ss[warp][0] = lsum; ss[warp][1] = lsq; }
    __syncthreads();
    if (tid == 0) {
        float s = 0.f, q = 0.f;
        #pragma unroll
        for (int w = 0; w < WARPS_K1; ++w) { s += ss[w][0]; q += ss[w][1]; }
        g_part[b][blockIdx.x][0] = s;
        g_part[b][blockIdx.x][1] = q;
    }
}

// ---------------------------------------------------------------------------
// Kernel 2: per-batch mean/var, sigmoid transform, icov/det/mean.
// One block per batch. Writes the mean & det output segments.
// ---------------------------------------------------------------------------
__global__ __launch_bounds__(256) void k2(float* __restrict__ out_mean,
                                          float* __restrict__ out_det)
{
    const int b   = blockIdx.x;
    const int tid = threadIdx.x;

    __shared__ float sa[256], sb[256];
    float s = 0.f, q = 0.f;
    if (tid < BLOCKS_PER_BATCH) { s = g_part[b][tid][0]; q = g_part[b][tid][1]; }
    sa[tid] = s; sb[tid] = q;
    __syncthreads();
    #pragma unroll
    for (int off = 128; off; off >>= 1) {
        if (tid < off) { sa[tid] += sa[tid + off]; sb[tid] += sb[tid + off]; }
        __syncthreads();
    }
    const float n    = (float)(HW * 2);
    const float mu   = sa[0] / n;
    const float var  = sb[0] / n - mu * mu + 1e-5f;
    const float rstd = rsqrtf(var);

    for (int i = tid; i < HW; i += 256) {
        float v0 = (g_v[b][i][0] - mu) * rstd;
        float v1 = (g_v[b][i][1] - mu) * rstd;
        v0 = 5.f / (1.f + __expf(-v0)) + 0.05f;   // sigmoid*5 + 0.05
        v1 = 5.f / (1.f + __expf(-v1)) + 0.05f;
        const float det   = v0 * v1;
        const float scale = 3.0f / (6.28f * sqrtf(det));
        const float m0 = (float)(i % 48) + g_mo[b][i][0];
        const float m1 = (float)(i / 48) + g_mo[b][i][1];

        g_prm[b][i][0] = 1.f / v0;
        g_prm[b][i][1] = 1.f / v1;
        g_prm[b][i][2] = scale;
        g_prm[b][i][3] = m0;
        g_prm[b][i][4] = m1;

        out_mean[((long)b * HW + i) * 2 + 0] = m0;
        out_mean[((long)b * HW + i) * 2 + 1] = m1;
        out_det [(long)b * HW + i]           = det;
    }
}

// ---------------------------------------------------------------------------
// Kernel 3: pdf[b,i,j]. Separable: 48 x-exps and 48 y-exps in smem,
// then 576 float4 coalesced stores per row. One block per (b,i).
// ---------------------------------------------------------------------------
__global__ __launch_bounds__(288) void k3(float* __restrict__ out_pdf)
{
    const int i = blockIdx.x;
    const int b = blockIdx.y;
    const int tid = threadIdx.x;

    const float ic0   = g_prm[b][i][0];
    const float ic1   = g_prm[b][i][1];
    const float scale = g_prm[b][i][2];
    const float m0    = g_prm[b][i][3];
    const float m1    = g_prm[b][i][4];

    __shared__ float ex[48], ey[48];
    if (tid < 48) {
        float d = (float)tid - m0;
        ex[tid] = __expf(-0.5f * d * d * ic0) * scale;   // fold scale into x-axis
    } else if (tid < 96) {
        float d = (float)(tid - 48) - m1;
        ey[tid - 48] = __expf(-0.5f * d * d * ic1);
    }
    __syncthreads();

    float4* dst = (float4*)(out_pdf + ((long)b * HW + i) * HW);
    #pragma unroll
    for (int it = 0; it < 2; ++it) {                     // 576 / 288 == 2
        const int j4 = tid + it * 288;
        const int j  = j4 * 4;
        const int y  = j / 48;
        const int x0 = j % 48;                           // 48 % 4 == 0 → same y, x..x+3
        const float e = ey[y];
        float4 v;
        v.x = ex[x0 + 0] * e;
        v.y = ex[x0 + 1] * e;
        v.z = ex[x0 + 2] * e;
        v.w = ex[x0 + 3] * e;
        dst[j4] = v;
    }
}

// ---------------------------------------------------------------------------
extern "C" void kernel_launch(void* const* d_in, const int* in_sizes, int n_in,
                              void* d_out, int out_size)
{
    const float* x      = (const float*)d_in[0];
    const float* map_w  = (const float*)d_in[1];
    const float* map_b  = (const float*)d_in[2];
    const float* mean_w = (const float*)d_in[3];
    const float* mean_b = (const float*)d_in[4];
    const float* cov_w  = (const float*)d_in[5];
    const float* cov_b  = (const float*)d_in[6];

    float* out      = (float*)d_out;
    float* out_pdf  = out;                                  // 4*2304*2304
    float* out_mean = out + (long)NB * HW * HW;             // 4*2304*2
    float* out_det  = out_mean + (long)NB * HW * 2;         // 4*2304

    dim3 g1(BLOCKS_PER_BATCH, NB);
    k1<<<g1, 256>>>(x, map_w, map_b, mean_w, mean_b, cov_w, cov_b);
    k2<<<NB, 256>>>(out_mean, out_det);
    dim3 g3(HW, NB);
    k3<<<g3, 288>>>(out_pdf);
}

// round 3
// speedup vs baseline: 1.6792x; 1.6792x over previous
#include <cuda_runtime.h>
#include <cuda_bf16.h>

#define HW   2304
#define CIN  256
#define CMID 16
#define NB   4
#define K1_WARPS 8
#define PIX_PER_BLOCK (K1_WARPS * 4)              // 32
#define BLOCKS_PER_BATCH (HW / PIX_PER_BLOCK)     // 72

// Scratch (static device globals — no allocations allowed)
__device__ float g_v  [NB][HW][2];
__device__ float g_mo [NB][HW][2];
__device__ float g_part[NB][BLOCKS_PER_BATCH][2];
__device__ float g_prm[NB][HW][5];   // ic0, ic1, scale, m0, m1

// ---------------------------------------------------------------------------
// Kernel 1: per-pixel 256->16 projection, tanh, 16->2 projections,
//           per-block partial sums for the batch normalization.
// One warp handles 4 pixels simultaneously (register-blocked).
// ---------------------------------------------------------------------------
__global__ __launch_bounds__(256) void k1(
    const float* __restrict__ x,
    const float* __restrict__ map_w,  const float* __restrict__ map_b,
    const float* __restrict__ mean_w, const float* __restrict__ mean_b,
    const float* __restrict__ cov_w,  const float* __restrict__ cov_b)
{
    __shared__ float sw[CMID * CIN];        // 16 KB of weights
    const int b    = blockIdx.y;
    const int tid  = threadIdx.x;
    const int warp = tid >> 5;
    const int lane = tid & 31;

    // stage weights (float4)
    {
        const float4* src = (const float4*)map_w;
        float4* dst = (float4*)sw;
        #pragma unroll
        for (int i = 0; i < 4; ++i) dst[tid + 256 * i] = src[tid + 256 * i];
    }
    __syncthreads();

    const int pix0 = (blockIdx.x * K1_WARPS + warp) * 4;
    const float* xb = x + ((long)b * HW + pix0) * CIN;

    // 4 pixel rows, 8 floats per lane each (two float4)
    float4 xv0[4], xv1[4];
    #pragma unroll
    for (int p = 0; p < 4; ++p) {
        const float4* row = (const float4*)(xb + p * CIN);
        xv0[p] = row[lane];
        xv1[p] = row[lane + 32];
    }

    float acc[4][16];
    const float4* sw4 = (const float4*)sw;
    #pragma unroll
    for (int c = 0; c < CMID; ++c) {
        const float4 w0 = sw4[c * 64 + lane];
        const float4 w1 = sw4[c * 64 + 32 + lane];
        #pragma unroll
        for (int p = 0; p < 4; ++p) {
            float a;
            a = xv0[p].x * w0.x;
            a = fmaf(xv0[p].y, w0.y, a);
            a = fmaf(xv0[p].z, w0.z, a);
            a = fmaf(xv0[p].w, w0.w, a);
            a = fmaf(xv1[p].x, w1.x, a);
            a = fmaf(xv1[p].y, w1.y, a);
            a = fmaf(xv1[p].z, w1.z, a);
            a = fmaf(xv1[p].w, w1.w, a);
            acc[p][c] = a;
        }
    }

    // Halving butterfly: 16 values -> 1 per lane within each 16-lane half.
    // After 4 stages, lane holds channel bitrev4(lane&15), half-partial.
    #pragma unroll
    for (int st = 0; st < 4; ++st) {
        const int off = 1 << st;
        const bool up = (lane >> st) & 1;
        const int half = 8 >> st;             // n/2 for n = 16>>st
        #pragma unroll
        for (int p = 0; p < 4; ++p) {
            #pragma unroll
            for (int i = 0; i < 8; ++i) {
                if (i < half) {
                    float send  = up ? acc[p][i] : acc[p][i + half];
                    float other = __shfl_xor_sync(0xffffffffu, send, off);
                    float keep  = up ? acc[p][i + half] : acc[p][i];
                    acc[p][i] = keep + other;
                }
            }
        }
    }
    // combine the two 16-lane halves
    #pragma unroll
    for (int p = 0; p < 4; ++p)
        acc[p][0] += __shfl_xor_sync(0xffffffffu, acc[p][0], 16);

    // channel owned by this lane: bit-reverse of lane[3:0]
    const int ch = ((lane & 1) << 3) | ((lane & 2) << 1)
                 | ((lane & 4) >> 1) | ((lane & 8) >> 3);
    const float mb  = __ldg(&map_b[ch]);
    const float wm0 = __ldg(&mean_w[ch]);
    const float wm1 = __ldg(&mean_w[CMID + ch]);
    const float wc0 = __ldg(&cov_w[ch]);
    const float wc1 = __ldg(&cov_w[CMID + ch]);
    const float mb0 = __ldg(&mean_b[0]), mb1 = __ldg(&mean_b[1]);
    const float cb0 = __ldg(&cov_b[0]),  cb1 = __ldg(&cov_b[1]);

    float lsum = 0.f, lsq = 0.f;
    float mo0v[4], mo1v[4], v0v[4], v1v[4];
    #pragma unroll
    for (int p = 0; p < 4; ++p) {
        const float t = tanhf(acc[p][0] + mb);
        float pm0 = t * wm0, pm1 = t * wm1, pv0 = t * wc0, pv1 = t * wc1;
        #pragma unroll
        for (int off = 1; off <= 8; off <<= 1) {
            pm0 += __shfl_xor_sync(0xffffffffu, pm0, off);
            pm1 += __shfl_xor_sync(0xffffffffu, pm1, off);
            pv0 += __shfl_xor_sync(0xffffffffu, pv0, off);
            pv1 += __shfl_xor_sync(0xffffffffu, pv1, off);
        }
        mo0v[p] = pm0 + mb0;  mo1v[p] = pm1 + mb1;
        v0v[p]  = pv0 + cb0;  v1v[p]  = pv1 + cb1;
        lsum += v0v[p] + v1v[p];
        lsq  += v0v[p] * v0v[p] + v1v[p] * v1v[p];
    }

    if (lane == 0) {
        #pragma unroll
        for (int p = 0; p < 4; ++p) {
            g_mo[b][pix0 + p][0] = mo0v[p];
            g_mo[b][pix0 + p][1] = mo1v[p];
            g_v [b][pix0 + p][0] = v0v[p];
            g_v [b][pix0 + p][1] = v1v[p];
        }
    }

    __shared__ float ss[K1_WARPS][2];
    if (lane == 0) { ss[warp][0] = lsum; ss[warp][1] = lsq; }
    __syncthreads();
    if (tid == 0) {
        float s = 0.f, q = 0.f;
        #pragma unroll
        for (int w = 0; w < K1_WARPS; ++w) { s += ss[w][0]; q += ss[w][1]; }
        g_part[b][blockIdx.x][0] = s;
        g_part[b][blockIdx.x][1] = q;
    }
}

// ---------------------------------------------------------------------------
// Kernel 2: per-batch mean/var, sigmoid transform, icov/det/mean.
// One block per batch. Writes the mean & det output segments.
// ---------------------------------------------------------------------------
__global__ __launch_bounds__(256) void k2(float* __restrict__ out_mean,
                                          float* __restrict__ out_det)
{
    const int b   = blockIdx.x;
    const int tid = threadIdx.x;

    __shared__ float sa[256], sb[256];
    float s = 0.f, q = 0.f;
    if (tid < BLOCKS_PER_BATCH) { s = g_part[b][tid][0]; q = g_part[b][tid][1]; }
    sa[tid] = s; sb[tid] = q;
    __syncthreads();
    #pragma unroll
    for (int off = 128; off; off >>= 1) {
        if (tid < off) { sa[tid] += sa[tid + off]; sb[tid] += sb[tid + off]; }
        __syncthreads();
    }
    const float n    = (float)(HW * 2);
    const float mu   = sa[0] / n;
    const float var  = sb[0] / n - mu * mu + 1e-5f;
    const float rstd = rsqrtf(var);

    for (int i = tid; i < HW; i += 256) {
        float v0 = (g_v[b][i][0] - mu) * rstd;
        float v1 = (g_v[b][i][1] - mu) * rstd;
        v0 = 5.f / (1.f + __expf(-v0)) + 0.05f;   // sigmoid*5 + 0.05
        v1 = 5.f / (1.f + __expf(-v1)) + 0.05f;
        const float det   = v0 * v1;
        const float scale = 3.0f / (6.28f * sqrtf(det));
        const float m0 = (float)(i % 48) + g_mo[b][i][0];
        const float m1 = (float)(i / 48) + g_mo[b][i][1];

        g_prm[b][i][0] = 1.f / v0;
        g_prm[b][i][1] = 1.f / v1;
        g_prm[b][i][2] = scale;
        g_prm[b][i][3] = m0;
        g_prm[b][i][4] = m1;

        out_mean[((long)b * HW + i) * 2 + 0] = m0;
        out_mean[((long)b * HW + i) * 2 + 1] = m1;
        out_det [(long)b * HW + i]           = det;
    }
}

// ---------------------------------------------------------------------------
// Kernel 3: pdf[b,i,j]. Separable: 48 x-exps and 48 y-exps in smem,
// then 576 float4 coalesced streaming stores per row. One block per (b,i).
// ---------------------------------------------------------------------------
__global__ __launch_bounds__(576) void k3(float* __restrict__ out_pdf)
{
    const int i = blockIdx.x;
    const int b = blockIdx.y;
    const int tid = threadIdx.x;

    __shared__ float ex[48], ey[48];
    if (tid < 48) {
        const float ic0   = g_prm[b][i][0];
        const float scale = g_prm[b][i][2];
        const float m0    = g_prm[b][i][3];
        float d = (float)tid - m0;
        ex[tid] = __expf(-0.5f * d * d * ic0) * scale;   // fold scale into x-axis
    } else if (tid < 96) {
        const float ic1 = g_prm[b][i][1];
        const float m1  = g_prm[b][i][4];
        float d = (float)(tid - 48) - m1;
        ey[tid - 48] = __expf(-0.5f * d * d * ic1);
    }
    __syncthreads();

    float4* dst = (float4*)(out_pdf + ((long)b * HW + i) * HW);
    const int j  = tid * 4;
    const int y  = j / 48;
    const int x0 = j % 48;                               // 48 % 4 == 0 → same y row
    const float e = ey[y];
    float4 v;
    v.x = ex[x0 + 0] * e;
    v.y = ex[x0 + 1] * e;
    v.z = ex[x0 + 2] * e;
    v.w = ex[x0 + 3] * e;
    __stcs(dst + tid, v);
}

// ---------------------------------------------------------------------------
extern "C" void kernel_launch(void* const* d_in, const int* in_sizes, int n_in,
                              void* d_out, int out_size)
{
    const float* x      = (const float*)d_in[0];
    const float* map_w  = (const float*)d_in[1];
    const float* map_b  = (const float*)d_in[2];
    const float* mean_w = (const float*)d_in[3];
    const float* mean_b = (const float*)d_in[4];
    const float* cov_w  = (const float*)d_in[5];
    const float* cov_b  = (const float*)d_in[6];

    float* out      = (float*)d_out;
    float* out_pdf  = out;                                  // 4*2304*2304
    float* out_mean = out + (long)NB * HW * HW;             // 4*2304*2
    float* out_det  = out_mean + (long)NB * HW * 2;         // 4*2304

    dim3 g1(BLOCKS_PER_BATCH, NB);
    k1<<<g1, 256>>>(x, map_w, map_b, mean_w, mean_b, cov_w, cov_b);
    k2<<<NB, 256>>>(out_mean, out_det);
    dim3 g3(HW, NB);
    k3<<<g3, 576>>>(out_pdf);
}

// round 4
// speedup vs baseline: 2.0020x; 1.1922x over previous
#include <cuda_runtime.h>
#include <cuda_bf16.h>

#define HW   2304
#define CIN  256
#define CMID 16
#define NB   4
#define K1_WARPS 8
#define PIX_PER_WARP 2
#define PIX_PER_BLOCK (K1_WARPS * PIX_PER_WARP)   // 16
#define BLOCKS_PER_BATCH (HW / PIX_PER_BLOCK)     // 144
#define ROWS_K3 4

// Scratch (static device globals — no allocations allowed)
__device__ float g_v  [NB][HW][2];
__device__ float g_mo [NB][HW][2];
__device__ float g_part[NB][BLOCKS_PER_BATCH][2];
__device__ float g_prm[NB][HW][5];   // ic0, ic1, scale, m0, m1

// ---------------------------------------------------------------------------
// Kernel 1: per-pixel 256->16 projection, tanh, 16->2 projections,
//           per-block partial sums for the batch normalization.
// One warp handles 2 pixels (register-blocked, ~70 regs -> 3 blocks/SM).
// ---------------------------------------------------------------------------
__global__ __launch_bounds__(256) void k1(
    const float* __restrict__ x,
    const float* __restrict__ map_w,  const float* __restrict__ map_b,
    const float* __restrict__ mean_w, const float* __restrict__ mean_b,
    const float* __restrict__ cov_w,  const float* __restrict__ cov_b)
{
    __shared__ float sw[CMID * CIN];        // 16 KB of weights
    const int b    = blockIdx.y;
    const int tid  = threadIdx.x;
    const int warp = tid >> 5;
    const int lane = tid & 31;

    // stage weights (float4)
    {
        const float4* src = (const float4*)map_w;
        float4* dst = (float4*)sw;
        #pragma unroll
        for (int i = 0; i < 4; ++i) dst[tid + 256 * i] = src[tid + 256 * i];
    }
    __syncthreads();

    const int pix0 = (blockIdx.x * K1_WARPS + warp) * PIX_PER_WARP;
    const float* xb = x + ((long)b * HW + pix0) * CIN;

    float4 xv0[PIX_PER_WARP], xv1[PIX_PER_WARP];
    #pragma unroll
    for (int p = 0; p < PIX_PER_WARP; ++p) {
        const float4* row = (const float4*)(xb + p * CIN);
        xv0[p] = row[lane];
        xv1[p] = row[lane + 32];
    }

    float acc[PIX_PER_WARP][16];
    const float4* sw4 = (const float4*)sw;
    #pragma unroll
    for (int c = 0; c < CMID; ++c) {
        const float4 w0 = sw4[c * 64 + lane];
        const float4 w1 = sw4[c * 64 + 32 + lane];
        #pragma unroll
        for (int p = 0; p < PIX_PER_WARP; ++p) {
            float a;
            a = xv0[p].x * w0.x;
            a = fmaf(xv0[p].y, w0.y, a);
            a = fmaf(xv0[p].z, w0.z, a);
            a = fmaf(xv0[p].w, w0.w, a);
            a = fmaf(xv1[p].x, w1.x, a);
            a = fmaf(xv1[p].y, w1.y, a);
            a = fmaf(xv1[p].z, w1.z, a);
            a = fmaf(xv1[p].w, w1.w, a);
            acc[p][c] = a;
        }
    }

    // Halving butterfly: 16 values -> 1 per lane within each 16-lane half.
    // After 4 stages, lane holds channel bitrev4(lane&15), half-partial.
    #pragma unroll
    for (int st = 0; st < 4; ++st) {
        const int off = 1 << st;
        const bool up = (lane >> st) & 1;
        const int half = 8 >> st;
        #pragma unroll
        for (int p = 0; p < PIX_PER_WARP; ++p) {
            #pragma unroll
            for (int i = 0; i < 8; ++i) {
                if (i < half) {
                    float send  = up ? acc[p][i] : acc[p][i + half];
                    float other = __shfl_xor_sync(0xffffffffu, send, off);
                    float keep  = up ? acc[p][i + half] : acc[p][i];
                    acc[p][i] = keep + other;
                }
            }
        }
    }
    #pragma unroll
    for (int p = 0; p < PIX_PER_WARP; ++p)
        acc[p][0] += __shfl_xor_sync(0xffffffffu, acc[p][0], 16);

    // channel owned by this lane: bit-reverse of lane[3:0]
    const int ch = ((lane & 1) << 3) | ((lane & 2) << 1)
                 | ((lane & 4) >> 1) | ((lane & 8) >> 3);
    const float mb  = __ldg(&map_b[ch]);
    const float wm0 = __ldg(&mean_w[ch]);
    const float wm1 = __ldg(&mean_w[CMID + ch]);
    const float wc0 = __ldg(&cov_w[ch]);
    const float wc1 = __ldg(&cov_w[CMID + ch]);
    const float mb0 = __ldg(&mean_b[0]), mb1 = __ldg(&mean_b[1]);
    const float cb0 = __ldg(&cov_b[0]),  cb1 = __ldg(&cov_b[1]);

    float lsum = 0.f, lsq = 0.f;
    float mo0v[PIX_PER_WARP], mo1v[PIX_PER_WARP];
    float v0v[PIX_PER_WARP],  v1v[PIX_PER_WARP];
    #pragma unroll
    for (int p = 0; p < PIX_PER_WARP; ++p) {
        const float t = tanhf(acc[p][0] + mb);
        float pm0 = t * wm0, pm1 = t * wm1, pv0 = t * wc0, pv1 = t * wc1;
        #pragma unroll
        for (int off = 1; off <= 8; off <<= 1) {
            pm0 += __shfl_xor_sync(0xffffffffu, pm0, off);
            pm1 += __shfl_xor_sync(0xffffffffu, pm1, off);
            pv0 += __shfl_xor_sync(0xffffffffu, pv0, off);
            pv1 += __shfl_xor_sync(0xffffffffu, pv1, off);
        }
        mo0v[p] = pm0 + mb0;  mo1v[p] = pm1 + mb1;
        v0v[p]  = pv0 + cb0;  v1v[p]  = pv1 + cb1;
        lsum += v0v[p] + v1v[p];
        lsq  += v0v[p] * v0v[p] + v1v[p] * v1v[p];
    }

    if (lane == 0) {
        #pragma unroll
        for (int p = 0; p < PIX_PER_WARP; ++p) {
            g_mo[b][pix0 + p][0] = mo0v[p];
            g_mo[b][pix0 + p][1] = mo1v[p];
            g_v [b][pix0 + p][0] = v0v[p];
            g_v [b][pix0 + p][1] = v1v[p];
        }
    }

    __shared__ float ss[K1_WARPS][2];
    if (lane == 0) { ss[warp][0] = lsum; ss[warp][1] = lsq; }
    __syncthreads();
    if (tid == 0) {
        float s = 0.f, q = 0.f;
        #pragma unroll
        for (int w = 0; w < K1_WARPS; ++w) { s += ss[w][0]; q += ss[w][1]; }
        g_part[b][blockIdx.x][0] = s;
        g_part[b][blockIdx.x][1] = q;
    }
}

// ---------------------------------------------------------------------------
// Kernel 2: per-batch mean/var, sigmoid transform, icov/det/mean.
// One block per batch. Writes the mean & det output segments.
// ---------------------------------------------------------------------------
__global__ __launch_bounds__(256) void k2(float* __restrict__ out_mean,
                                          float* __restrict__ out_det)
{
    const int b   = blockIdx.x;
    const int tid = threadIdx.x;

    __shared__ float sa[256], sb[256];
    float s = 0.f, q = 0.f;
    if (tid < BLOCKS_PER_BATCH) { s = g_part[b][tid][0]; q = g_part[b][tid][1]; }
    sa[tid] = s; sb[tid] = q;
    __syncthreads();
    #pragma unroll
    for (int off = 128; off; off >>= 1) {
        if (tid < off) { sa[tid] += sa[tid + off]; sb[tid] += sb[tid + off]; }
        __syncthreads();
    }
    const float n    = (float)(HW * 2);
    const float mu   = sa[0] / n;
    const float var  = sb[0] / n - mu * mu + 1e-5f;
    const float rstd = rsqrtf(var);

    for (int i = tid; i < HW; i += 256) {
        float v0 = (g_v[b][i][0] - mu) * rstd;
        float v1 = (g_v[b][i][1] - mu) * rstd;
        v0 = 5.f / (1.f + __expf(-v0)) + 0.05f;   // sigmoid*5 + 0.05
        v1 = 5.f / (1.f + __expf(-v1)) + 0.05f;
        const float det   = v0 * v1;
        const float scale = 3.0f / (6.28f * sqrtf(det));
        const float m0 = (float)(i % 48) + g_mo[b][i][0];
        const float m1 = (float)(i / 48) + g_mo[b][i][1];

        g_prm[b][i][0] = 1.f / v0;
        g_prm[b][i][1] = 1.f / v1;
        g_prm[b][i][2] = scale;
        g_prm[b][i][3] = m0;
        g_prm[b][i][4] = m1;

        out_mean[((long)b * HW + i) * 2 + 0] = m0;
        out_mean[((long)b * HW + i) * 2 + 1] = m1;
        out_det [(long)b * HW + i]           = det;
    }
}

// ---------------------------------------------------------------------------
// Kernel 3: pdf[b,i,j]. Separable Gaussian, 4 rows per block.
// 384 threads: exp phase uses all threads (4 rows x 96 exps), then
// 6 float4 streaming stores per thread over a contiguous 36KB chunk.
// ---------------------------------------------------------------------------
__global__ __launch_bounds__(384) void k3(float* __restrict__ out_pdf)
{
    const int i0  = blockIdx.x * ROWS_K3;
    const int b   = blockIdx.y;
    const int tid = threadIdx.x;

    __shared__ __align__(16) float ex[ROWS_K3][48];
    __shared__ float ey[ROWS_K3][48];

    {
        const int r = tid / 96;
        const int k = tid - r * 96;
        const int i = i0 + r;
        if (k < 48) {
            const float d = (float)k - g_prm[b][i][3];
            ex[r][k] = __expf(-0.5f * d * d * g_prm[b][i][0]) * g_prm[b][i][2];
        } else {
            const float d = (float)(k - 48) - g_prm[b][i][4];
            ey[r][k - 48] = __expf(-0.5f * d * d * g_prm[b][i][1]);
        }
    }
    __syncthreads();

    float4* dst = (float4*)(out_pdf + ((long)b * HW + i0) * HW);
    #pragma unroll
    for (int s = 0; s < 6; ++s) {                 // 4*576 / 384 = 6
        const int j4 = tid + 384 * s;
        const int r  = j4 / 576;
        const int jr = j4 - r * 576;              // float4 index within row
        const int y  = jr / 12;                   // 12 float4 per x-line
        const int x4 = jr - y * 12;
        const float e  = ey[r][y];
        const float4 vx = *(const float4*)&ex[r][x4 * 4];
        float4 v;
        v.x = vx.x * e;  v.y = vx.y * e;  v.z = vx.z * e;  v.w = vx.w * e;
        __stcs(dst + j4, v);
    }
}

// ---------------------------------------------------------------------------
extern "C" void kernel_launch(void* const* d_in, const int* in_sizes, int n_in,
                              void* d_out, int out_size)
{
    const float* x      = (const float*)d_in[0];
    const float* map_w  = (const float*)d_in[1];
    const float* map_b  = (const float*)d_in[2];
    const float* mean_w = (const float*)d_in[3];
    const float* mean_b = (const float*)d_in[4];
    const float* cov_w  = (const float*)d_in[5];
    const float* cov_b  = (const float*)d_in[6];

    float* out      = (float*)d_out;
    float* out_pdf  = out;                                  // 4*2304*2304
    float* out_mean = out + (long)NB * HW * HW;             // 4*2304*2
    float* out_det  = out_mean + (long)NB * HW * 2;         // 4*2304

    dim3 g1(BLOCKS_PER_BATCH, NB);
    k1<<<g1, 256>>>(x, map_w, map_b, mean_w, mean_b, cov_w, cov_b);
    k2<<<NB, 256>>>(out_mean, out_det);
    dim3 g3(HW / ROWS_K3, NB);
    k3<<<g3, 384>>>(out_pdf);
}

// round 7
// speedup vs baseline: 2.4371x; 1.2173x over previous
#include <cuda_runtime.h>
#include <cuda_bf16.h>

#define HW   2304
#define CIN  256
#define CMID 16
#define NB   4
#define K1_WARPS 4
#define PIX_PER_WARP 4
#define PIX_PER_BLOCK (K1_WARPS * PIX_PER_WARP)   // 16
#define BLOCKS_PER_BATCH (HW / PIX_PER_BLOCK)     // 144
#define ROWS_K3 4

// Scratch (static device globals — no allocations allowed)
__device__ float g_v  [NB][HW][2];
__device__ float g_mo [NB][HW][2];
__device__ float g_part[NB][BLOCKS_PER_BATCH][2];

// ---------------------------------------------------------------------------
// Kernel 1: per-pixel 256->16 projection, tanh, 16->2 projections,
//           per-block partial sums for the batch normalization.
// 4 pixels per warp (max weight reuse), 128-thread blocks (grid 576 for
// balanced waves and 4 blocks/SM).
// ---------------------------------------------------------------------------
__global__ __launch_bounds__(128) void k1(
    const float* __restrict__ x,
    const float* __restrict__ map_w,  const float* __restrict__ map_b,
    const float* __restrict__ mean_w, const float* __restrict__ mean_b,
    const float* __restrict__ cov_w,  const float* __restrict__ cov_b)
{
    __shared__ float sw[CMID * CIN];        // 16 KB of weights
    const int b    = blockIdx.y;
    const int tid  = threadIdx.x;
    const int warp = tid >> 5;
    const int lane = tid & 31;

    // stage weights (float4): 1024 float4 / 128 threads = 8 each
    {
        const float4* src = (const float4*)map_w;
        float4* dst = (float4*)sw;
        #pragma unroll
        for (int i = 0; i < 8; ++i) dst[tid + 128 * i] = src[tid + 128 * i];
    }
    __syncthreads();

    const int pix0 = (blockIdx.x * K1_WARPS + warp) * PIX_PER_WARP;
    const float* xb = x + ((long)b * HW + pix0) * CIN;

    // 4 pixel rows, 8 floats per lane each (two float4)
    float4 xv0[PIX_PER_WARP], xv1[PIX_PER_WARP];
    #pragma unroll
    for (int p = 0; p < PIX_PER_WARP; ++p) {
        const float4* row = (const float4*)(xb + p * CIN);
        xv0[p] = row[lane];
        xv1[p] = row[lane + 32];
    }

    float acc[PIX_PER_WARP][16];
    const float4* sw4 = (const float4*)sw;
    #pragma unroll
    for (int c = 0; c < CMID; ++c) {
        const float4 w0 = sw4[c * 64 + lane];
        const float4 w1 = sw4[c * 64 + 32 + lane];
        #pragma unroll
        for (int p = 0; p < PIX_PER_WARP; ++p) {
            float a;
            a = xv0[p].x * w0.x;
            a = fmaf(xv0[p].y, w0.y, a);
            a = fmaf(xv0[p].z, w0.z, a);
            a = fmaf(xv0[p].w, w0.w, a);
            a = fmaf(xv1[p].x, w1.x, a);
            a = fmaf(xv1[p].y, w1.y, a);
            a = fmaf(xv1[p].z, w1.z, a);
            a = fmaf(xv1[p].w, w1.w, a);
            acc[p][c] = a;
        }
    }

    // Halving butterfly: 16 values -> 1 per lane within each 16-lane half.
    // After 4 stages, lane holds channel bitrev4(lane&15), half-partial.
    #pragma unroll
    for (int st = 0; st < 4; ++st) {
        const int off = 1 << st;
        const bool up = (lane >> st) & 1;
        const int half = 8 >> st;
        #pragma unroll
        for (int p = 0; p < PIX_PER_WARP; ++p) {
            #pragma unroll
            for (int i = 0; i < 8; ++i) {
                if (i < half) {
                    float send  = up ? acc[p][i] : acc[p][i + half];
                    float other = __shfl_xor_sync(0xffffffffu, send, off);
                    float keep  = up ? acc[p][i + half] : acc[p][i];
                    acc[p][i] = keep + other;
                }
            }
        }
    }
    #pragma unroll
    for (int p = 0; p < PIX_PER_WARP; ++p)
        acc[p][0] += __shfl_xor_sync(0xffffffffu, acc[p][0], 16);

    // channel owned by this lane: bit-reverse of lane[3:0]
    const int ch = ((lane & 1) << 3) | ((lane & 2) << 1)
                 | ((lane & 4) >> 1) | ((lane & 8) >> 3);
    const float mb  = __ldg(&map_b[ch]);
    const float wm0 = __ldg(&mean_w[ch]);
    const float wm1 = __ldg(&mean_w[CMID + ch]);
    const float wc0 = __ldg(&cov_w[ch]);
    const float wc1 = __ldg(&cov_w[CMID + ch]);
    const float mb0 = __ldg(&mean_b[0]), mb1 = __ldg(&mean_b[1]);
    const float cb0 = __ldg(&cov_b[0]),  cb1 = __ldg(&cov_b[1]);

    float lsum = 0.f, lsq = 0.f;
    float mo0v[PIX_PER_WARP], mo1v[PIX_PER_WARP];
    float v0v[PIX_PER_WARP],  v1v[PIX_PER_WARP];
    #pragma unroll
    for (int p = 0; p < PIX_PER_WARP; ++p) {
        const float t = tanhf(acc[p][0] + mb);
        float pm0 = t * wm0, pm1 = t * wm1, pv0 = t * wc0, pv1 = t * wc1;
        #pragma unroll
        for (int off = 1; off <= 8; off <<= 1) {
            pm0 += __shfl_xor_sync(0xffffffffu, pm0, off);
            pm1 += __shfl_xor_sync(0xffffffffu, pm1, off);
            pv0 += __shfl_xor_sync(0xffffffffu, pv0, off);
            pv1 += __shfl_xor_sync(0xffffffffu, pv1, off);
        }
        mo0v[p] = pm0 + mb0;  mo1v[p] = pm1 + mb1;
        v0v[p]  = pv0 + cb0;  v1v[p]  = pv1 + cb1;
        lsum += v0v[p] + v1v[p];
        lsq  += v0v[p] * v0v[p] + v1v[p] * v1v[p];
    }

    if (lane == 0) {
        #pragma unroll
        for (int p = 0; p < PIX_PER_WARP; ++p) {
            g_mo[b][pix0 + p][0] = mo0v[p];
            g_mo[b][pix0 + p][1] = mo1v[p];
            g_v [b][pix0 + p][0] = v0v[p];
            g_v [b][pix0 + p][1] = v1v[p];
        }
    }

    __shared__ float ss[K1_WARPS][2];
    if (lane == 0) { ss[warp][0] = lsum; ss[warp][1] = lsq; }
    __syncthreads();
    if (tid == 0) {
        float s = 0.f, q = 0.f;
        #pragma unroll
        for (int w = 0; w < K1_WARPS; ++w) { s += ss[w][0]; q += ss[w][1]; }
        g_part[b][blockIdx.x][0] = s;
        g_part[b][blockIdx.x][1] = q;
    }
}

// ---------------------------------------------------------------------------
// Kernel 3 (k2 merged in): each block redundantly reduces the 144 per-block
// partials (warp 0, L2-resident), computes its 4 rows' params, writes the
// mean/det output rows, then the separable pdf tile.
// ---------------------------------------------------------------------------
__global__ __launch_bounds__(384) void k3(float* __restrict__ out_pdf,
                                          float* __restrict__ out_mean,
                                          float* __restrict__ out_det)
{
    const int i0  = blockIdx.x * ROWS_K3;
    const int b   = blockIdx.y;
    const int tid = threadIdx.x;
    const int lane = tid & 31;

    __shared__ __align__(16) float ex[ROWS_K3][48];
    __shared__ float ey[ROWS_K3][48];
    __shared__ float prm[ROWS_K3][5];   // ic0, ic1, scale, m0, m1

    if (tid < 32) {
        float s = 0.f, q = 0.f;
        for (int e = lane; e < BLOCKS_PER_BATCH; e += 32) {
            s += g_part[b][e][0];
            q += g_part[b][e][1];
        }
        #pragma unroll
        for (int off = 16; off; off >>= 1) {
            s += __shfl_xor_sync(0xffffffffu, s, off);
            q += __shfl_xor_sync(0xffffffffu, q, off);
        }
        const float n    = (float)(HW * 2);
        const float mu   = s / n;
        const float rstd = rsqrtf(q / n - mu * mu + 1e-5f);

        if (lane < ROWS_K3) {
            const int i = i0 + lane;
            float v0 = (g_v[b][i][0] - mu) * rstd;
            float v1 = (g_v[b][i][1] - mu) * rstd;
            v0 = 5.f / (1.f + __expf(-v0)) + 0.05f;   // sigmoid*5 + 0.05
            v1 = 5.f / (1.f + __expf(-v1)) + 0.05f;
            const float det   = v0 * v1;
            const float scale = 3.0f / (6.28f * sqrtf(det));
            const float m0 = (float)(i % 48) + g_mo[b][i][0];
            const float m1 = (float)(i / 48) + g_mo[b][i][1];
            prm[lane][0] = 1.f / v0;
            prm[lane][1] = 1.f / v1;
            prm[lane][2] = scale;
            prm[lane][3] = m0;
            prm[lane][4] = m1;
            out_mean[((long)b * HW + i) * 2 + 0] = m0;
            out_mean[((long)b * HW + i) * 2 + 1] = m1;
            out_det [(long)b * HW + i]           = det;
        }
    }
    __syncthreads();

    {
        const int r = tid / 96;
        const int k = tid - r * 96;
        if (k < 48) {
            const float d = (float)k - prm[r][3];
            ex[r][k] = __expf(-0.5f * d * d * prm[r][0]) * prm[r][2];
        } else {
            const float d = (float)(k - 48) - prm[r][4];
            ey[r][k - 48] = __expf(-0.5f * d * d * prm[r][1]);
        }
    }
    __syncthreads();

    float4* dst = (float4*)(out_pdf + ((long)b * HW + i0) * HW);
    #pragma unroll
    for (int s = 0; s < 6; ++s) {                 // 4*576 / 384 = 6
        const int j4 = tid + 384 * s;
        const int r  = j4 / 576;
        const int jr = j4 - r * 576;              // float4 index within row
        const int y  = jr / 12;                   // 12 float4 per x-line
        const int x4 = jr - y * 12;
        const float e  = ey[r][y];
        const float4 vx = *(const float4*)&ex[r][x4 * 4];
        float4 v;
        v.x = vx.x * e;  v.y = vx.y * e;  v.z = vx.z * e;  v.w = vx.w * e;
        __stcs(dst + j4, v);
    }
}

// ---------------------------------------------------------------------------
extern "C" void kernel_launch(void* const* d_in, const int* in_sizes, int n_in,
                              void* d_out, int out_size)
{
    const float* x      = (const float*)d_in[0];
    const float* map_w  = (const float*)d_in[1];
    const float* map_b  = (const float*)d_in[2];
    const float* mean_w = (const float*)d_in[3];
    const float* mean_b = (const float*)d_in[4];
    const float* cov_w  = (const float*)d_in[5];
    const float* cov_b  = (const float*)d_in[6];

    float* out      = (float*)d_out;
    float* out_pdf  = out;                                  // 4*2304*2304
    float* out_mean = out + (long)NB * HW * HW;             // 4*2304*2
    float* out_det  = out_mean + (long)NB * HW * 2;         // 4*2304

    dim3 g1(BLOCKS_PER_BATCH, NB);
    k1<<<g1, 128>>>(x, map_w, map_b, mean_w, mean_b, cov_w, cov_b);
    dim3 g3(HW / ROWS_K3, NB);
    k3<<<g3, 384>>>(out_pdf, out_mean, out_det);
}